// round 16
// baseline (speedup 1.0000x reference)
#include <cuda_runtime.h>
#include <cuda_bf16.h>
#include <cstdint>

#define NN      96
#define NPOS    57600
#define NITERS  5
#define FEPS    1e-20f
#define PT      64
#define NBLK    (NPOS / PT)        // 900
#define NTHR    128
#define NCH     25

#define WFRAG_U2 1536              // per-chunk W image: wj only (uint2)

__device__ __align__(16) uint2    g_wfrag[NCH * WFRAG_U2];   // 307 KB, L2-resident
__device__ __align__(16) uint32_t g_xb[16 * 32 * 4096];      // 8 MB bf16x2 channel pairs
__device__ float g_csum[16 * 4096];
__device__ float g_invs[NPOS];

// ---------------- helpers ----------------
__device__ __forceinline__ float frcp(float x) {
    float r; asm("rcp.approx.ftz.f32 %0, %1;" : "=f"(r) : "f"(x)); return r;
}
__device__ __forceinline__ uint32_t packbf(float lo, float hi) {
    uint32_t r;
    asm("cvt.rn.bf16x2.f32 %0, %1, %2;" : "=r"(r) : "f"(hi), "f"(lo));
    return r;
}
__device__ __forceinline__ float bflo(uint32_t v) { return __uint_as_float(v << 16); }
__device__ __forceinline__ float bfhi(uint32_t v) { return __uint_as_float(v & 0xFFFF0000u); }
__device__ __forceinline__ uint32_t movm(uint32_t a) {
    uint32_t d;
    asm("movmatrix.sync.aligned.m8n8.trans.b16 %0, %1;" : "=r"(d) : "r"(a));
    return d;
}

__device__ __forceinline__ void mma_bf16(float c[4], const uint32_t a[4],
                                         uint32_t b0, uint32_t b1) {
    asm("mma.sync.aligned.m16n8k16.row.col.f32.bf16.bf16.f32 "
        "{%0,%1,%2,%3}, {%4,%5,%6,%7}, {%8,%9}, {%0,%1,%2,%3};"
        : "+f"(c[0]), "+f"(c[1]), "+f"(c[2]), "+f"(c[3])
        : "r"(a[0]), "r"(a[1]), "r"(a[2]), "r"(a[3]), "r"(b0), "r"(b1));
}

// ---------------- precompute ----------------
__global__ void csum_kernel(const float* __restrict__ x) {
    int idx = blockIdx.x * blockDim.x + threadIdx.x;
    if (idx >= 16 * 4096) return;
    int b = idx >> 12, p = idx & 4095;
    const float* xp = x + (size_t)b * 64 * 4096 + p;
    float s = 0.f;
    #pragma unroll
    for (int c = 0; c < 64; ++c) s += xp[c * 4096];
    g_csum[idx] = s;
}
__global__ void invs_kernel() {
    int idx = blockIdx.x * blockDim.x + threadIdx.x;
    if (idx >= NPOS) return;
    int b = idx / 3600, r = idx % 3600, y = r / 60, xp = r % 60;
    float s = 0.f;
    #pragma unroll
    for (int ki = 0; ki < 5; ++ki)
        #pragma unroll
        for (int kj = 0; kj < 5; ++kj) s += g_csum[b * 4096 + (y + ki) * 64 + (xp + kj)];
    g_invs[idx] = 1.0f / (s + FEPS);
}

// packed bf16 channel-pair image: g_xb[b][c2][pix] = bf16x2(x[2c2], x[2c2+1])
__global__ void xb_kernel(const float* __restrict__ x) {
    int idx = blockIdx.x * blockDim.x + threadIdx.x;
    if (idx >= 16 * 32 * 4096) return;
    int b = idx >> 17, r = idx & 131071, c2 = r >> 12, p = r & 4095;
    const float* xp = x + ((size_t)(b * 64 + 2 * c2)) * 4096 + p;
    g_xb[idx] = packbf(xp[0], xp[4096]);
}

// Wj fragment image only: frag (s,dt) at (s*8+dt)*32+lane, B-layout (k=n, col=d)
__global__ void wfrag_kernel(const float* __restrict__ w) {
    int idx = blockIdx.x * blockDim.x + threadIdx.x;
    if (idx >= NCH * WFRAG_U2) return;
    int kk = idx / WFRAG_U2, r = idx % WFRAG_U2;
    int lane = r & 31, t = r >> 5;       // t = s*8 + dt
    int gid = lane >> 2, tig = lane & 3;
    int s = t >> 3, dt = t & 7;
    int row = (dt * 8 + gid) * NCH + kk;     // W row for channel d
    int n0 = s * 16 + tig * 2;
    uint2 v;
    v.x = packbf(w[row * NN + n0],     w[row * NN + n0 + 1]);
    v.y = packbf(w[row * NN + n0 + 8], w[row * NN + n0 + 9]);
    g_wfrag[idx] = v;
}

// ---------------- main HMMA kernel (no smem, no syncs in hot loop) ----------------
__global__ void __launch_bounds__(NTHR, 3)
nnmf_hmma(float* __restrict__ out) {
    const int tid  = threadIdx.x;
    const int warp = tid >> 5;
    const int lane = tid & 31;
    const int gid  = lane >> 2;
    const int tig  = lane & 3;

    // position decompose for this thread's two C-fragment rows
    const int p0 = blockIdx.x * PT + warp * 16 + gid;
    const int p1 = p0 + 8;
    const int b0 = p0 / 3600, rem0 = p0 - b0 * 3600;
    const int y0 = rem0 / 60,  x0  = rem0 - y0 * 60;
    const int b1 = p1 / 3600, rem1 = p1 - b1 * 3600;
    const int y1 = rem1 / 60,  x1  = rem1 - y1 * 60;
    const float inv0 = g_invs[p0];
    const float inv1 = g_invs[p1];
    const uint32_t* q0 = g_xb + b0 * 131072 + tig * 4096 + y0 * 64 + x0;
    const uint32_t* q1 = g_xb + b1 * 131072 + tig * 4096 + y1 * 64 + x1;

    float hc[12][4];
    #pragma unroll
    for (int t = 0; t < 12; ++t)
        #pragma unroll
        for (int e = 0; e < 4; ++e) hc[t][e] = 1.0f / 96.0f;

    for (int it = 0; it < NITERS; ++it) {
        uint32_t hA[6][4];
        #pragma unroll
        for (int s = 0; s < 6; ++s) {
            hA[s][0] = packbf(hc[2 * s][0],     hc[2 * s][1]);
            hA[s][1] = packbf(hc[2 * s][2],     hc[2 * s][3]);
            hA[s][2] = packbf(hc[2 * s + 1][0], hc[2 * s + 1][1]);
            hA[s][3] = packbf(hc[2 * s + 1][2], hc[2 * s + 1][3]);
        }
        float tc[12][4];
        #pragma unroll
        for (int t = 0; t < 12; ++t)
            #pragma unroll
            for (int e = 0; e < 4; ++e) tc[t][e] = 0.f;

        int koff = 0, kjc = 0;                 // ki*64 + kj, updated incrementally
        for (int j = 0; j < NCH; ++j) {
            const uint2* wj = g_wfrag + j * WFRAG_U2 + lane;

            // per dt-pair: 12 W-frag LDGs -> MMA1 -> ratio -> MMA2 (movm reuse)
            #pragma unroll
            for (int du = 0; du < 4; ++du) {
                const uint32_t* qa = q0 + koff + du * 32768;   // dt=2du, row gid
                const uint32_t* qb = q1 + koff + du * 32768;   // dt=2du, row gid+8
                const uint32_t u00 = __ldg(qa);
                const uint32_t u01 = __ldg(qb);
                const uint32_t u10 = __ldg(qa + 16384);        // dt=2du+1
                const uint32_t u11 = __ldg(qb + 16384);

                uint2 bf[6][2];
                #pragma unroll
                for (int s = 0; s < 6; ++s) {
                    bf[s][0] = __ldg(wj + (s * 8 + 2 * du) * 32);
                    bf[s][1] = __ldg(wj + (s * 8 + 2 * du + 1) * 32);
                }

                float d0[4] = {0.f, 0.f, 0.f, 0.f};
                float d1[4] = {0.f, 0.f, 0.f, 0.f};
                #pragma unroll
                for (int s = 0; s < 6; ++s) {
                    mma_bf16(d0, hA[s], bf[s][0].x, bf[s][0].y);
                    mma_bf16(d1, hA[s], bf[s][1].x, bf[s][1].y);
                }

                const float r00 = bflo(u00) * inv0 * frcp(d0[0] + FEPS);
                const float r01 = bfhi(u00) * inv0 * frcp(d0[1] + FEPS);
                const float r02 = bflo(u01) * inv1 * frcp(d0[2] + FEPS);
                const float r03 = bfhi(u01) * inv1 * frcp(d0[3] + FEPS);
                const float r10 = bflo(u10) * inv0 * frcp(d1[0] + FEPS);
                const float r11 = bfhi(u10) * inv0 * frcp(d1[1] + FEPS);
                const float r12 = bflo(u11) * inv1 * frcp(d1[2] + FEPS);
                const float r13 = bfhi(u11) * inv1 * frcp(d1[3] + FEPS);
                uint32_t ra[4];
                ra[0] = packbf(r00, r01);
                ra[1] = packbf(r02, r03);
                ra[2] = packbf(r10, r11);
                ra[3] = packbf(r12, r13);

                // MMA2: T += R * Wt, Wt fragments = movmatrix of the regs we hold
                #pragma unroll
                for (int v = 0; v < 6; ++v) {
                    mma_bf16(tc[2 * v],     ra, movm(bf[v][0].x), movm(bf[v][1].x));
                    mma_bf16(tc[2 * v + 1], ra, movm(bf[v][0].y), movm(bf[v][1].y));
                }
            }

            if (++kjc == 5) { kjc = 0; koff += 60; } else { ++koff; }
        }

        // h = h*(1+t); h /= (sum_n h + eps)
        float s0 = 0.f, s1 = 0.f;
        #pragma unroll
        for (int t = 0; t < 12; ++t) {
            hc[t][0] = fmaf(hc[t][0], tc[t][0], hc[t][0]);
            hc[t][1] = fmaf(hc[t][1], tc[t][1], hc[t][1]);
            hc[t][2] = fmaf(hc[t][2], tc[t][2], hc[t][2]);
            hc[t][3] = fmaf(hc[t][3], tc[t][3], hc[t][3]);
            s0 += hc[t][0] + hc[t][1];
            s1 += hc[t][2] + hc[t][3];
        }
        s0 += __shfl_xor_sync(0xffffffffu, s0, 1);
        s1 += __shfl_xor_sync(0xffffffffu, s1, 1);
        s0 += __shfl_xor_sync(0xffffffffu, s0, 2);
        s1 += __shfl_xor_sync(0xffffffffu, s1, 2);
        const float rs0 = frcp(s0 + FEPS);
        const float rs1 = frcp(s1 + FEPS);
        #pragma unroll
        for (int t = 0; t < 12; ++t) {
            hc[t][0] *= rs0; hc[t][1] *= rs0;
            hc[t][2] *= rs1; hc[t][3] *= rs1;
        }
    }

    // output: out[b][n][pos]
    #pragma unroll
    for (int e = 0; e < 4; ++e) {
        const int p = (e >> 1) ? p1 : p0;
        const int b = (e >> 1) ? b1 : b0;
        const int pos = p - b * 3600;
        #pragma unroll
        for (int t = 0; t < 12; ++t) {
            const int n = t * 8 + 2 * tig + (e & 1);
            out[((size_t)(b * NN + n)) * 3600 + pos] = hc[t][e];
        }
    }
}

// ---------------- launch ----------------
extern "C" void kernel_launch(void* const* d_in, const int* in_sizes, int n_in,
                              void* d_out, int out_size) {
    const float* x = (const float*)d_in[0];
    const float* w = (const float*)d_in[1];
    if (n_in >= 2 && in_sizes[0] == 1600 * NN) { const float* t = x; x = w; w = t; }
    float* out = (float*)d_out;

    csum_kernel<<<(16 * 4096 + 255) / 256, 256>>>(x);
    invs_kernel<<<(NPOS + 255) / 256, 256>>>();
    wfrag_kernel<<<(NCH * WFRAG_U2 + 255) / 256, 256>>>(w);
    xb_kernel<<<(16 * 32 * 4096 + 255) / 256, 256>>>(x);

    nnmf_hmma<<<NBLK, NTHR>>>(out);
}

// round 17
// speedup vs baseline: 1.4119x; 1.4119x over previous
#include <cuda_runtime.h>
#include <cuda_bf16.h>
#include <cstdint>

#define NN      96
#define NPOS    57600
#define NITERS  5
#define FEPS    1e-20f
#define PT      64
#define NBLK    (NPOS / PT)        // 900
#define NTHR    128
#define NCH     25

#define WFRAG_U2 1536              // per-chunk W image: wj only (uint2)
#define SMEM_BYTES (2 * WFRAG_U2 * 8)   // 24576

__device__ __align__(16) uint2    g_wfrag[NCH * WFRAG_U2];   // 307 KB
__device__ __align__(16) uint32_t g_xb[16 * 32 * 4096];      // 8 MB bf16x2 channel pairs
__device__ float g_csum[16 * 4096];
__device__ float g_invs[NPOS];

// ---------------- helpers ----------------
__device__ __forceinline__ float frcp(float x) {
    float r; asm("rcp.approx.ftz.f32 %0, %1;" : "=f"(r) : "f"(x)); return r;
}
__device__ __forceinline__ uint32_t packbf(float lo, float hi) {
    uint32_t r;
    asm("cvt.rn.bf16x2.f32 %0, %1, %2;" : "=r"(r) : "f"(hi), "f"(lo));
    return r;
}
__device__ __forceinline__ float bflo(uint32_t v) { return __uint_as_float(v << 16); }
__device__ __forceinline__ float bfhi(uint32_t v) { return __uint_as_float(v & 0xFFFF0000u); }
__device__ __forceinline__ uint32_t movm(uint32_t a) {
    uint32_t d;
    asm("movmatrix.sync.aligned.m8n8.trans.b16 %0, %1;" : "=r"(d) : "r"(a));
    return d;
}

__device__ __forceinline__ void mma_bf16(float c[4], const uint32_t a[4],
                                         uint32_t b0, uint32_t b1) {
    asm("mma.sync.aligned.m16n8k16.row.col.f32.bf16.bf16.f32 "
        "{%0,%1,%2,%3}, {%4,%5,%6,%7}, {%8,%9}, {%0,%1,%2,%3};"
        : "+f"(c[0]), "+f"(c[1]), "+f"(c[2]), "+f"(c[3])
        : "r"(a[0]), "r"(a[1]), "r"(a[2]), "r"(a[3]), "r"(b0), "r"(b1));
}

__device__ __forceinline__ void cp16(uint32_t dst_smem, const void* src) {
    asm volatile("cp.async.cg.shared.global [%0], [%1], 16;" :: "r"(dst_smem), "l"(src));
}
#define CP_COMMIT() asm volatile("cp.async.commit_group;")
template <int N> __device__ __forceinline__ void cp_wait() {
    asm volatile("cp.async.wait_group %0;" :: "n"(N));
}
__device__ __forceinline__ void cp_chunk(uint2* dst, const uint2* src, int tid) {
    uint32_t d0 = (uint32_t)__cvta_generic_to_shared(dst);
    #pragma unroll
    for (int i = 0; i < 6; ++i) {          // 1536 * 8B / 16B / 128 thr
        int j = tid + i * NTHR;
        cp16(d0 + j * 16, src + j * 2);
    }
}

// ---------------- precompute ----------------
__global__ void csum_kernel(const float* __restrict__ x) {
    int idx = blockIdx.x * blockDim.x + threadIdx.x;
    if (idx >= 16 * 4096) return;
    int b = idx >> 12, p = idx & 4095;
    const float* xp = x + (size_t)b * 64 * 4096 + p;
    float s = 0.f;
    #pragma unroll
    for (int c = 0; c < 64; ++c) s += xp[c * 4096];
    g_csum[idx] = s;
}
__global__ void invs_kernel() {
    int idx = blockIdx.x * blockDim.x + threadIdx.x;
    if (idx >= NPOS) return;
    int b = idx / 3600, r = idx % 3600, y = r / 60, xp = r % 60;
    float s = 0.f;
    #pragma unroll
    for (int ki = 0; ki < 5; ++ki)
        #pragma unroll
        for (int kj = 0; kj < 5; ++kj) s += g_csum[b * 4096 + (y + ki) * 64 + (xp + kj)];
    g_invs[idx] = 1.0f / (s + FEPS);
}

// packed bf16 channel-pair image: g_xb[b][c2][pix] = bf16x2(x[2c2], x[2c2+1])
__global__ void xb_kernel(const float* __restrict__ x) {
    int idx = blockIdx.x * blockDim.x + threadIdx.x;
    if (idx >= 16 * 32 * 4096) return;
    int b = idx >> 17, r = idx & 131071, c2 = r >> 12, p = r & 4095;
    const float* xp = x + ((size_t)(b * 64 + 2 * c2)) * 4096 + p;
    g_xb[idx] = packbf(xp[0], xp[4096]);
}

// Wj fragment image only: frag (s,dt) at (s*8+dt)*32+lane, B-layout (k=n, col=d)
__global__ void wfrag_kernel(const float* __restrict__ w) {
    int idx = blockIdx.x * blockDim.x + threadIdx.x;
    if (idx >= NCH * WFRAG_U2) return;
    int kk = idx / WFRAG_U2, r = idx % WFRAG_U2;
    int lane = r & 31, t = r >> 5;       // t = s*8 + dt
    int gid = lane >> 2, tig = lane & 3;
    int s = t >> 3, dt = t & 7;
    int row = (dt * 8 + gid) * NCH + kk;     // W row for channel d
    int n0 = s * 16 + tig * 2;
    uint2 v;
    v.x = packbf(w[row * NN + n0],     w[row * NN + n0 + 1]);
    v.y = packbf(w[row * NN + n0 + 8], w[row * NN + n0 + 9]);
    g_wfrag[idx] = v;
}

// ---------------- main HMMA kernel ----------------
extern __shared__ __align__(16) uint2 ws[];   // [2][1536]

__global__ void __launch_bounds__(NTHR, 3)
nnmf_hmma(float* __restrict__ out) {
    const int tid  = threadIdx.x;
    const int warp = tid >> 5;
    const int lane = tid & 31;
    const int gid  = lane >> 2;
    const int tig  = lane & 3;

    cp_chunk(ws, g_wfrag, tid);
    CP_COMMIT();

    // position decompose for this thread's two C-fragment rows
    const int p0 = blockIdx.x * PT + warp * 16 + gid;
    const int p1 = p0 + 8;
    const int b0 = p0 / 3600, rem0 = p0 - b0 * 3600;
    const int y0 = rem0 / 60,  x0  = rem0 - y0 * 60;
    const int b1 = p1 / 3600, rem1 = p1 - b1 * 3600;
    const int y1 = rem1 / 60,  x1  = rem1 - y1 * 60;
    const float inv0 = g_invs[p0];
    const float inv1 = g_invs[p1];
    const uint32_t* q0 = g_xb + b0 * 131072 + tig * 4096 + y0 * 64 + x0;
    const uint32_t* q1 = g_xb + b1 * 131072 + tig * 4096 + y1 * 64 + x1;

    float hc[12][4];
    #pragma unroll
    for (int t = 0; t < 12; ++t)
        #pragma unroll
        for (int e = 0; e < 4; ++e) hc[t][e] = 1.0f / 96.0f;

    for (int it = 0; it < NITERS; ++it) {
        uint32_t hA[6][4];
        #pragma unroll
        for (int s = 0; s < 6; ++s) {
            hA[s][0] = packbf(hc[2 * s][0],     hc[2 * s][1]);
            hA[s][1] = packbf(hc[2 * s][2],     hc[2 * s][3]);
            hA[s][2] = packbf(hc[2 * s + 1][0], hc[2 * s + 1][1]);
            hA[s][3] = packbf(hc[2 * s + 1][2], hc[2 * s + 1][3]);
        }
        float tc[12][4];
        #pragma unroll
        for (int t = 0; t < 12; ++t)
            #pragma unroll
            for (int e = 0; e < 4; ++e) tc[t][e] = 0.f;

        int koff = 0, kjc = 0;                 // ki*64 + kj, updated incrementally
        for (int j = 0; j < NCH; ++j) {
            const int cs = it * NCH + j;
            const uint2* wb = ws + (cs & 1) * WFRAG_U2;
            if (cs < NITERS * NCH - 1) {
                cp_chunk(ws + ((cs + 1) & 1) * WFRAG_U2,
                         g_wfrag + ((j + 1) % NCH) * WFRAG_U2, tid);
                CP_COMMIT();
                cp_wait<1>();
            } else {
                cp_wait<0>();
            }
            __syncthreads();

            // hoist ALL x loads for this chunk: latency overlaps MMA1 below
            uint32_t u[4][4];
            #pragma unroll
            for (int du = 0; du < 4; ++du) {
                const uint32_t* qa = q0 + koff + du * 32768;
                const uint32_t* qb = q1 + koff + du * 32768;
                u[du][0] = __ldg(qa);
                u[du][1] = __ldg(qb);
                u[du][2] = __ldg(qa + 16384);
                u[du][3] = __ldg(qb + 16384);
            }

            // MMA1 + ratio, streamed per dt-pair
            uint32_t rA[4][4];
            #pragma unroll
            for (int du = 0; du < 4; ++du) {
                float d0[4] = {0.f, 0.f, 0.f, 0.f};
                float d1[4] = {0.f, 0.f, 0.f, 0.f};
                #pragma unroll
                for (int s = 0; s < 6; ++s) {
                    uint2 f0 = wb[(s * 8 + 2 * du) * 32 + lane];
                    uint2 f1 = wb[(s * 8 + 2 * du + 1) * 32 + lane];
                    mma_bf16(d0, hA[s], f0.x, f0.y);
                    mma_bf16(d1, hA[s], f1.x, f1.y);
                }
                const float r00 = bflo(u[du][0]) * inv0 * frcp(d0[0] + FEPS);
                const float r01 = bfhi(u[du][0]) * inv0 * frcp(d0[1] + FEPS);
                const float r02 = bflo(u[du][1]) * inv1 * frcp(d0[2] + FEPS);
                const float r03 = bfhi(u[du][1]) * inv1 * frcp(d0[3] + FEPS);
                const float r10 = bflo(u[du][2]) * inv0 * frcp(d1[0] + FEPS);
                const float r11 = bfhi(u[du][2]) * inv0 * frcp(d1[1] + FEPS);
                const float r12 = bflo(u[du][3]) * inv1 * frcp(d1[2] + FEPS);
                const float r13 = bfhi(u[du][3]) * inv1 * frcp(d1[3] + FEPS);
                rA[du][0] = packbf(r00, r01);
                rA[du][1] = packbf(r02, r03);
                rA[du][2] = packbf(r10, r11);
                rA[du][3] = packbf(r12, r13);
            }

            // MMA2: T += R * Wt, Wt fragments derived from Wj via movmatrix
            #pragma unroll
            for (int v = 0; v < 6; ++v) {
                #pragma unroll
                for (int sd = 0; sd < 4; ++sd) {
                    uint2 f0 = wb[(v * 8 + 2 * sd) * 32 + lane];
                    uint2 f1 = wb[(v * 8 + 2 * sd + 1) * 32 + lane];
                    mma_bf16(tc[2 * v],     rA[sd], movm(f0.x), movm(f1.x));
                    mma_bf16(tc[2 * v + 1], rA[sd], movm(f0.y), movm(f1.y));
                }
            }
            __syncthreads();

            if (++kjc == 5) { kjc = 0; koff += 60; } else { ++koff; }
        }

        // h = h*(1+t); h /= (sum_n h + eps)
        float s0 = 0.f, s1 = 0.f;
        #pragma unroll
        for (int t = 0; t < 12; ++t) {
            hc[t][0] = fmaf(hc[t][0], tc[t][0], hc[t][0]);
            hc[t][1] = fmaf(hc[t][1], tc[t][1], hc[t][1]);
            hc[t][2] = fmaf(hc[t][2], tc[t][2], hc[t][2]);
            hc[t][3] = fmaf(hc[t][3], tc[t][3], hc[t][3]);
            s0 += hc[t][0] + hc[t][1];
            s1 += hc[t][2] + hc[t][3];
        }
        s0 += __shfl_xor_sync(0xffffffffu, s0, 1);
        s1 += __shfl_xor_sync(0xffffffffu, s1, 1);
        s0 += __shfl_xor_sync(0xffffffffu, s0, 2);
        s1 += __shfl_xor_sync(0xffffffffu, s1, 2);
        const float rs0 = frcp(s0 + FEPS);
        const float rs1 = frcp(s1 + FEPS);
        #pragma unroll
        for (int t = 0; t < 12; ++t) {
            hc[t][0] *= rs0; hc[t][1] *= rs0;
            hc[t][2] *= rs1; hc[t][3] *= rs1;
        }
    }

    // output: out[b][n][pos]
    #pragma unroll
    for (int e = 0; e < 4; ++e) {
        const int p = (e >> 1) ? p1 : p0;
        const int b = (e >> 1) ? b1 : b0;
        const int pos = p - b * 3600;
        #pragma unroll
        for (int t = 0; t < 12; ++t) {
            const int n = t * 8 + 2 * tig + (e & 1);
            out[((size_t)(b * NN + n)) * 3600 + pos] = hc[t][e];
        }
    }
}

// ---------------- launch ----------------
extern "C" void kernel_launch(void* const* d_in, const int* in_sizes, int n_in,
                              void* d_out, int out_size) {
    const float* x = (const float*)d_in[0];
    const float* w = (const float*)d_in[1];
    if (n_in >= 2 && in_sizes[0] == 1600 * NN) { const float* t = x; x = w; w = t; }
    float* out = (float*)d_out;

    csum_kernel<<<(16 * 4096 + 255) / 256, 256>>>(x);
    invs_kernel<<<(NPOS + 255) / 256, 256>>>();
    wfrag_kernel<<<(NCH * WFRAG_U2 + 255) / 256, 256>>>(w);
    xb_kernel<<<(16 * 32 * 4096 + 255) / 256, 256>>>(x);

    cudaFuncSetAttribute(nnmf_hmma, cudaFuncAttributeMaxDynamicSharedMemorySize, SMEM_BYTES);
    nnmf_hmma<<<NBLK, NTHR, SMEM_BYTES>>>(out);
}